// round 1
// baseline (speedup 1.0000x reference)
#include <cuda_runtime.h>
#include <cstdint>
#include <cstddef>

// Problem constants
#define BB 4
#define SS 4096
#define HH 768
#define RR 242
#define HK 256
#define CP 256          // padded channel dim for rank-242 intermediates
#define RWIN 16         // attention band half-width (everything beyond underflows to 0 in fp32)
#define NFREQ 384       // H/2 rope frequencies

// ---------------- device scratch (allowed: __device__ globals, zero-initialized) ---------
__device__ float g_z [(size_t)BB * SS * CP];   // x @ v_low^T   (padded to 256)
__device__ float g_z2[(size_t)BB * SS * CP];   // band-mixed z
__device__ float g_T1t[RR * RR];               // o_low @ v_high
__device__ float g_WcT[HH * CP];               // o_high @ T1t  (row m: Wc^T[m, i], padded)
__device__ float g_e[RWIN + 1];                // attention band weights e(d) = exp(g(d)-384)

// ---------------- band weight precompute -------------------------------------------------
// warp w computes g(d=w) = sum_j cos(d * f_j), f_j = 10000^(-j/384); e(d) = exp(g - 384)
__global__ void prep_kernel() {
    int w    = threadIdx.x >> 5;
    int lane = threadIdx.x & 31;
    if (w > RWIN) return;
    float d = (float)w;
    float s = 0.f;
    for (int j = lane; j < NFREQ; j += 32) {
        float f = expf(-(float)j * (9.210340371976184f / (float)NFREQ)); // ln(10000)/384
        s += cosf(d * f);
    }
    #pragma unroll
    for (int o = 16; o > 0; o >>= 1) s += __shfl_down_sync(0xffffffffu, s, o);
    if (lane == 0) g_e[w] = expf(s - (float)NFREQ);
}

// ---------------- small NN gemm: C[M,N] = A[M,K] @ B[K,N] --------------------------------
__global__ void gemm_nn_small(const float* __restrict__ A, int lda,
                              const float* __restrict__ B, int ldb,
                              float* __restrict__ C, int ldc,
                              int M, int N, int K) {
    __shared__ float As[16][17];
    __shared__ float Bs[16][17];
    int tx = threadIdx.x, ty = threadIdx.y;
    int m = blockIdx.y * 16 + ty;
    int n = blockIdx.x * 16 + tx;
    float acc = 0.f;
    for (int k0 = 0; k0 < K; k0 += 16) {
        As[ty][tx] = (m < M && (k0 + tx) < K) ? A[(size_t)m * lda + k0 + tx] : 0.f;
        Bs[ty][tx] = ((k0 + ty) < K && n < N) ? B[(size_t)(k0 + ty) * ldb + n] : 0.f;
        __syncthreads();
        #pragma unroll
        for (int k = 0; k < 16; k++) acc += As[ty][k] * Bs[k][tx];
        __syncthreads();
    }
    if (m < M && n < N) C[(size_t)m * ldc + n] = acc;
}

// ---------------- main gemm: C[M,N] = A[M,K] @ B[N,K]^T ----------------------------------
// BM=BN=128, BK=16, 256 threads, 8x8 per thread. Requires: M%128==0, K%16==0,
// grid.x = N/128 exactly, lda/ldb/ldc multiples of 4, pointers 16B aligned.
// Rows of B with index >= Nb are treated as zero.
__global__ __launch_bounds__(256)
void gemm_abt(const float* __restrict__ A, int lda,
              const float* __restrict__ B, int ldb, int Nb,
              float* __restrict__ C, int ldc,
              int M, int K) {
    constexpr int BM = 128, BN = 128, BK = 16;
    __shared__ float As[BK][BM];
    __shared__ float Bs[BK][BN];
    const int tid = threadIdx.x;
    const int m0 = blockIdx.y * BM;
    const int n0 = blockIdx.x * BN;
    const int tx = tid & 15;      // 0..15 (N dir)
    const int ty = tid >> 4;      // 0..15 (M dir)
    float acc[8][8] = {};

    for (int k0 = 0; k0 < K; k0 += BK) {
        // load A tile (128 x 16) as float4, transpose into As[k][m]
        #pragma unroll
        for (int l = 0; l < 2; l++) {
            int f = tid + l * 256;
            int r = f >> 2;
            int c = (f & 3) << 2;
            float4 v = *(const float4*)(A + (size_t)(m0 + r) * lda + k0 + c);
            As[c + 0][r] = v.x; As[c + 1][r] = v.y; As[c + 2][r] = v.z; As[c + 3][r] = v.w;
        }
        // load B tile (128 x 16), zero-fill rows >= Nb
        #pragma unroll
        for (int l = 0; l < 2; l++) {
            int f = tid + l * 256;
            int r = f >> 2;
            int c = (f & 3) << 2;
            float4 v = make_float4(0.f, 0.f, 0.f, 0.f);
            if (n0 + r < Nb) v = *(const float4*)(B + (size_t)(n0 + r) * ldb + k0 + c);
            Bs[c + 0][r] = v.x; Bs[c + 1][r] = v.y; Bs[c + 2][r] = v.z; Bs[c + 3][r] = v.w;
        }
        __syncthreads();
        #pragma unroll
        for (int k = 0; k < BK; k++) {
            float ra[8], rb[8];
            *(float4*)&ra[0] = *(const float4*)&As[k][ty * 8];
            *(float4*)&ra[4] = *(const float4*)&As[k][ty * 8 + 4];
            *(float4*)&rb[0] = *(const float4*)&Bs[k][tx * 8];
            *(float4*)&rb[4] = *(const float4*)&Bs[k][tx * 8 + 4];
            #pragma unroll
            for (int i = 0; i < 8; i++)
                #pragma unroll
                for (int j = 0; j < 8; j++)
                    acc[i][j] += ra[i] * rb[j];
        }
        __syncthreads();
    }
    #pragma unroll
    for (int i = 0; i < 8; i++) {
        int gm = m0 + ty * 8 + i;
        #pragma unroll
        for (int j = 0; j < 8; j += 4) {
            int gn = n0 + tx * 8 + j;
            *(float4*)(C + (size_t)gm * ldc + gn) =
                make_float4(acc[i][j], acc[i][j + 1], acc[i][j + 2], acc[i][j + 3]);
        }
    }
}

// ---------------- banded softmax mix along sequence --------------------------------------
// z2[b,s,i] = (sum_d e(|d|) * z[b,s-d,i]) / (sum_d e(|d|)), d in [-W,W], 0 <= s-d < S
__global__ void mix_kernel(const float* __restrict__ z, float* __restrict__ z2) {
    int s = blockIdx.x;
    int b = blockIdx.y;
    int i = threadIdx.x;   // 0..255
    float Z = 0.f, acc = 0.f;
    #pragma unroll
    for (int d = -RWIN; d <= RWIN; ++d) {
        int t = s - d;
        if ((unsigned)t < (unsigned)SS) {
            float w = g_e[d < 0 ? -d : d];
            Z += w;
            acc += w * z[((size_t)b * SS + t) * CP + i];
        }
    }
    z2[((size_t)b * SS + s) * CP + i] = acc * (1.f / Z);
}

// ---------------- launch ------------------------------------------------------------------
extern "C" void kernel_launch(void* const* d_in, const int* in_sizes, int n_in,
                              void* d_out, int out_size) {
    const float* x      = (const float*)d_in[0];
    const float* v_low  = (const float*)d_in[5];   // [242, 768]
    const float* v_high = (const float*)d_in[6];   // [256, 242]
    const float* o_low  = (const float*)d_in[7];   // [242, 256]
    const float* o_high = (const float*)d_in[8];   // [768, 242]
    float* out = (float*)d_out;                    // [4, 4096, 768]

    float* z   = nullptr; cudaGetSymbolAddress((void**)&z,   g_z);
    float* z2  = nullptr; cudaGetSymbolAddress((void**)&z2,  g_z2);
    float* T1t = nullptr; cudaGetSymbolAddress((void**)&T1t, g_T1t);
    float* WcT = nullptr; cudaGetSymbolAddress((void**)&WcT, g_WcT);

    // 1. band weights e(d)
    prep_kernel<<<1, (RWIN + 1) * 32>>>();

    // 2. T1t[242,242] = o_low[242,256] @ v_high[256,242]
    gemm_nn_small<<<dim3((RR + 15) / 16, (RR + 15) / 16), dim3(16, 16)>>>(
        o_low, HK, v_high, RR, T1t, RR, RR, RR, HK);

    // 3. WcT[768,242(pad 256)] = o_high[768,242] @ T1t[242,242]
    gemm_nn_small<<<dim3((RR + 15) / 16, (HH + 15) / 16), dim3(16, 16)>>>(
        o_high, RR, T1t, RR, WcT, CP, HH, RR, RR);

    // 4. z[16384, 242(pad 256)] = x[16384,768] @ v_low[242,768]^T
    gemm_abt<<<dim3(CP / 128, (BB * SS) / 128), 256>>>(
        x, HH, v_low, HH, RR, z, CP, BB * SS, HH);

    // 5. banded softmax mix
    mix_kernel<<<dim3(SS, BB), CP>>>(z, z2);

    // 6. out[16384,768] = z2[16384,256] @ WcT[768,256]^T
    gemm_abt<<<dim3(HH / 128, (BB * SS) / 128), 256>>>(
        z2, CP, WcT, CP, HH, out, HH, BB * SS, CP);

    (void)in_sizes; (void)n_in; (void)out_size;
}

// round 3
// speedup vs baseline: 1.1769x; 1.1769x over previous
#include <cuda_runtime.h>
#include <cstdint>
#include <cstddef>

// Problem constants
#define BB 4
#define SS 4096
#define HH 768
#define RR 242
#define HK 256
#define CP 256
#define RWIN 16
#define NFREQ 384

// ---------------- device scratch ---------------------------------------------------------
__device__ float g_z [(size_t)BB * SS * CP];
__device__ float g_z2[(size_t)BB * SS * CP];
__device__ float g_T1t[RR * RR];
__device__ float g_WcT[HH * CP];
__device__ float g_e[RWIN + 1];

// ---------------- band weight precompute -------------------------------------------------
__global__ void prep_kernel() {
    int w    = threadIdx.x >> 5;
    int lane = threadIdx.x & 31;
    if (w > RWIN) return;
    float d = (float)w;
    float s = 0.f;
    for (int j = lane; j < NFREQ; j += 32) {
        float f = expf(-(float)j * (9.210340371976184f / (float)NFREQ));
        s += cosf(d * f);
    }
    #pragma unroll
    for (int o = 16; o > 0; o >>= 1) s += __shfl_down_sync(0xffffffffu, s, o);
    if (lane == 0) g_e[w] = expf(s - (float)NFREQ);
}

// ---------------- small NN gemm ----------------------------------------------------------
__global__ void gemm_nn_small(const float* __restrict__ A, int lda,
                              const float* __restrict__ B, int ldb,
                              float* __restrict__ C, int ldc,
                              int M, int N, int K) {
    __shared__ float As[16][17];
    __shared__ float Bs[16][17];
    int tx = threadIdx.x, ty = threadIdx.y;
    int m = blockIdx.y * 16 + ty;
    int n = blockIdx.x * 16 + tx;
    float acc = 0.f;
    for (int k0 = 0; k0 < K; k0 += 16) {
        As[ty][tx] = (m < M && (k0 + tx) < K) ? A[(size_t)m * lda + k0 + tx] : 0.f;
        Bs[ty][tx] = ((k0 + ty) < K && n < N) ? B[(size_t)(k0 + ty) * ldb + n] : 0.f;
        __syncthreads();
        #pragma unroll
        for (int k = 0; k < 16; k++) acc += As[ty][k] * Bs[k][tx];
        __syncthreads();
    }
    if (m < M && n < N) C[(size_t)m * ldc + n] = acc;
}

// ---------------- tf32 helpers -----------------------------------------------------------
__device__ __forceinline__ float cvt_tf32(float x) {
    float r;
    asm("cvt.rna.tf32.f32 %0, %1;" : "=f"(r) : "f"(x));
    return r;
}

__device__ __forceinline__ void mma_tf32(float* d, const uint32_t* a, const uint32_t* b) {
    asm volatile(
        "mma.sync.aligned.m16n8k8.row.col.f32.tf32.tf32.f32 "
        "{%0,%1,%2,%3}, {%4,%5,%6,%7}, {%8,%9}, {%0,%1,%2,%3};"
        : "+f"(d[0]), "+f"(d[1]), "+f"(d[2]), "+f"(d[3])
        : "r"(a[0]), "r"(a[1]), "r"(a[2]), "r"(a[3]), "r"(b[0]), "r"(b[1]));
}

// ---------------- tensor-core GEMM: C[M,N] = A[M,K] @ B[N,K]^T via 3xTF32 ----------------
// BM=128, BN=64, BK=32. 256 threads = 8 warps (4 M x 2 N). warp tile 32x32.
// M%128==0, K%32==0, grid.x*64 == N exactly. B rows >= Nb treated as zero.
#define BKP 36   // float2 row pitch with 32B pad -> conflict-free frag loads
#define SMA_F2 (128 * BKP)
#define SMB_F2 (64 * BKP)
#define SM_BYTES ((SMA_F2 + SMB_F2) * 8)

__global__ void __launch_bounds__(256)
mma_gemm_abt(const float* __restrict__ A, int lda,
             const float* __restrict__ B, int ldb, int Nb,
             float* __restrict__ C, int ldc, int K) {
    extern __shared__ float2 sm[];
    float2* Asm = sm;
    float2* Bsm = sm + SMA_F2;

    const int tid  = threadIdx.x;
    const int wid  = tid >> 5;
    const int lane = tid & 31;
    const int m0 = blockIdx.y * 128;
    const int n0 = blockIdx.x * 64;
    const int mbw = (wid & 3) * 32;   // warp M offset
    const int nbw = (wid >> 2) * 32;  // warp N offset
    const int lr = lane >> 2;         // 0..7
    const int lc = lane & 3;          // 0..3

    float acc[2][4][4] = {};          // [mtile][ntile][frag]

    const int nchunks = K >> 5;
    for (int ch = 0; ch < nchunks; ch++) {
        const int k0 = ch << 5;
        // ---- A tile: 128 x 32 fp32 -> (hi,lo) tf32 pairs ----
        #pragma unroll
        for (int i = 0; i < 4; i++) {
            int idx = tid + i * 256;         // 1024 float4 slots
            int r = idx >> 3, c4 = idx & 7;
            float4 v = *(const float4*)(A + (size_t)(m0 + r) * lda + k0 + c4 * 4);
            float h0 = cvt_tf32(v.x), h1 = cvt_tf32(v.y), h2 = cvt_tf32(v.z), h3 = cvt_tf32(v.w);
            float l0 = cvt_tf32(v.x - h0), l1 = cvt_tf32(v.y - h1);
            float l2 = cvt_tf32(v.z - h2), l3 = cvt_tf32(v.w - h3);
            float2* p = Asm + r * BKP + c4 * 4;
            *(float4*)(p + 0) = make_float4(h0, l0, h1, l1);
            *(float4*)(p + 2) = make_float4(h2, l2, h3, l3);
        }
        // ---- B tile: 64 x 32 fp32, rows >= Nb zero ----
        #pragma unroll
        for (int i = 0; i < 2; i++) {
            int idx = tid + i * 256;         // 512 float4 slots
            int r = idx >> 3, c4 = idx & 7;
            float4 v = make_float4(0.f, 0.f, 0.f, 0.f);
            if (n0 + r < Nb) v = *(const float4*)(B + (size_t)(n0 + r) * ldb + k0 + c4 * 4);
            float h0 = cvt_tf32(v.x), h1 = cvt_tf32(v.y), h2 = cvt_tf32(v.z), h3 = cvt_tf32(v.w);
            float l0 = cvt_tf32(v.x - h0), l1 = cvt_tf32(v.y - h1);
            float l2 = cvt_tf32(v.z - h2), l3 = cvt_tf32(v.w - h3);
            float2* p = Bsm + r * BKP + c4 * 4;
            *(float4*)(p + 0) = make_float4(h0, l0, h1, l1);
            *(float4*)(p + 2) = make_float4(h2, l2, h3, l3);
        }
        __syncthreads();

        #pragma unroll
        for (int ks = 0; ks < 4; ks++) {
            const int kk = ks * 8 + lc;
            // A fragments (hi,lo interleaved in float2)
            float2 af[2][4];
            #pragma unroll
            for (int t = 0; t < 2; t++) {
                int mr = mbw + t * 16 + lr;
                af[t][0] = Asm[mr * BKP + kk];
                af[t][1] = Asm[(mr + 8) * BKP + kk];
                af[t][2] = Asm[mr * BKP + kk + 4];
                af[t][3] = Asm[(mr + 8) * BKP + kk + 4];
            }
            // B fragments
            float2 bf[4][2];
            #pragma unroll
            for (int u = 0; u < 4; u++) {
                int nr = nbw + u * 8 + lr;
                bf[u][0] = Bsm[nr * BKP + kk];
                bf[u][1] = Bsm[nr * BKP + kk + 4];
            }
            #pragma unroll
            for (int t = 0; t < 2; t++) {
                uint32_t ah[4] = {__float_as_uint(af[t][0].x), __float_as_uint(af[t][1].x),
                                  __float_as_uint(af[t][2].x), __float_as_uint(af[t][3].x)};
                uint32_t al[4] = {__float_as_uint(af[t][0].y), __float_as_uint(af[t][1].y),
                                  __float_as_uint(af[t][2].y), __float_as_uint(af[t][3].y)};
                #pragma unroll
                for (int u = 0; u < 4; u++) {
                    uint32_t bh[2] = {__float_as_uint(bf[u][0].x), __float_as_uint(bf[u][1].x)};
                    uint32_t bl[2] = {__float_as_uint(bf[u][0].y), __float_as_uint(bf[u][1].y)};
                    mma_tf32(acc[t][u], ah, bh);
                    mma_tf32(acc[t][u], ah, bl);
                    mma_tf32(acc[t][u], al, bh);
                }
            }
        }
        __syncthreads();
    }

    // ---- epilogue ----
    #pragma unroll
    for (int t = 0; t < 2; t++) {
        int row = m0 + mbw + t * 16 + lr;
        #pragma unroll
        for (int u = 0; u < 4; u++) {
            int col = n0 + nbw + u * 8 + lc * 2;
            *(float2*)(C + (size_t)row * ldc + col) = make_float2(acc[t][u][0], acc[t][u][1]);
            *(float2*)(C + (size_t)(row + 8) * ldc + col) = make_float2(acc[t][u][2], acc[t][u][3]);
        }
    }
}

// ---------------- banded softmax mix, smem-tiled ------------------------------------------
// Block: 64 s-positions x 64 channels. smem holds 96 s-rows (halo 16 each side).
__global__ void __launch_bounds__(256)
mix_kernel(const float* __restrict__ z, float* __restrict__ z2) {
    __shared__ float zs[96][64];
    __shared__ float ws[2 * RWIN + 1];
    const int s0 = blockIdx.x * 64;
    const int c0 = blockIdx.y * 64;
    const int b  = blockIdx.z;
    const int tid = threadIdx.x;

    if (tid < 2 * RWIN + 1) ws[tid] = g_e[tid < RWIN ? RWIN - tid : tid - RWIN];

    // load 96 rows x 64 cols (global s = s0-16+row), OOB -> 0
    #pragma unroll
    for (int i = 0; i < 24; i++) {
        int idx = tid + i * 256;
        int r = idx >> 6, c = idx & 63;
        int gs = s0 - 16 + r;
        float v = 0.f;
        if ((unsigned)gs < (unsigned)SS)
            v = z[((size_t)b * SS + gs) * CP + c0 + c];
        zs[r][c] = v;
    }
    __syncthreads();

    const int c = tid & 63;
    #pragma unroll 4
    for (int is = 0; is < 16; is++) {
        int sl = (tid >> 6) + is * 4;         // 0..63
        int s = s0 + sl;
        float Z = 0.f, acc2 = 0.f;
        #pragma unroll
        for (int d = -RWIN; d <= RWIN; ++d) {
            int t = s - d;
            if ((unsigned)t < (unsigned)SS) {
                float w = ws[d + RWIN];
                Z += w;
                acc2 += w * zs[sl + 16 - d][c];
            }
        }
        z2[((size_t)b * SS + s) * CP + c0 + c] = acc2 * (1.f / Z);
    }
}

// ---------------- launch ------------------------------------------------------------------
extern "C" void kernel_launch(void* const* d_in, const int* in_sizes, int n_in,
                              void* d_out, int out_size) {
    const float* x      = (const float*)d_in[0];
    const float* v_low  = (const float*)d_in[5];   // [242, 768]
    const float* v_high = (const float*)d_in[6];   // [256, 242]
    const float* o_low  = (const float*)d_in[7];   // [242, 256]
    const float* o_high = (const float*)d_in[8];   // [768, 242]
    float* out = (float*)d_out;                    // [4, 4096, 768]

    float* z   = nullptr; cudaGetSymbolAddress((void**)&z,   g_z);
    float* z2  = nullptr; cudaGetSymbolAddress((void**)&z2,  g_z2);
    float* T1t = nullptr; cudaGetSymbolAddress((void**)&T1t, g_T1t);
    float* WcT = nullptr; cudaGetSymbolAddress((void**)&WcT, g_WcT);

    cudaFuncSetAttribute(mma_gemm_abt, cudaFuncAttributeMaxDynamicSharedMemorySize, SM_BYTES);

    // 1. band weights
    prep_kernel<<<1, (RWIN + 1) * 32>>>();

    // 2. T1t[242,242] = o_low[242,256] @ v_high[256,242]
    gemm_nn_small<<<dim3((RR + 15) / 16, (RR + 15) / 16), dim3(16, 16)>>>(
        o_low, HK, v_high, RR, T1t, RR, RR, RR, HK);

    // 3. WcT[768,242(pad 256)] = o_high[768,242] @ T1t[242,242]
    gemm_nn_small<<<dim3((RR + 15) / 16, (HH + 15) / 16), dim3(16, 16)>>>(
        o_high, RR, T1t, RR, WcT, CP, HH, RR, RR);

    // 4. z = x @ v_low^T   [16384, 256]
    mma_gemm_abt<<<dim3(CP / 64, (BB * SS) / 128), 256, SM_BYTES>>>(
        x, HH, v_low, HH, RR, z, CP, HH);

    // 5. banded softmax mix
    mix_kernel<<<dim3(SS / 64, CP / 64, BB), 256>>>(z, z2);

    // 6. out = z2 @ WcT^T  [16384, 768]
    mma_gemm_abt<<<dim3(HH / 64, (BB * SS) / 128), 256, SM_BYTES>>>(
        z2, CP, WcT, CP, HH, out, HH, CP);

    (void)in_sizes; (void)n_in; (void)out_size;
}

// round 4
// speedup vs baseline: 2.3279x; 1.9779x over previous
#include <cuda_runtime.h>
#include <cstdint>
#include <cstddef>

// Problem constants
#define BB 4
#define SS 4096
#define HH 768
#define RR 242
#define HK 256
#define CP 256
#define RWIN 16
#define NFREQ 384

// ---------------- device scratch ---------------------------------------------------------
__device__ float g_z [(size_t)BB * SS * CP];
__device__ float g_z2[(size_t)BB * SS * CP];
__device__ float g_T1t[RR * RR];
__device__ float g_WcT[HH * CP];
__device__ float g_e[RWIN + 1];

// ---------------- band weight precompute -------------------------------------------------
__global__ void prep_kernel() {
    int w    = threadIdx.x >> 5;
    int lane = threadIdx.x & 31;
    if (w > RWIN) return;
    float d = (float)w;
    float s = 0.f;
    for (int j = lane; j < NFREQ; j += 32) {
        float f = expf(-(float)j * (9.210340371976184f / (float)NFREQ));
        s += cosf(d * f);
    }
    #pragma unroll
    for (int o = 16; o > 0; o >>= 1) s += __shfl_down_sync(0xffffffffu, s, o);
    if (lane == 0) g_e[w] = expf(s - (float)NFREQ);
}

// ---------------- small NN gemm ----------------------------------------------------------
__global__ void gemm_nn_small(const float* __restrict__ A, int lda,
                              const float* __restrict__ B, int ldb,
                              float* __restrict__ C, int ldc,
                              int M, int N, int K) {
    __shared__ float As[16][17];
    __shared__ float Bs[16][17];
    int tx = threadIdx.x, ty = threadIdx.y;
    int m = blockIdx.y * 16 + ty;
    int n = blockIdx.x * 16 + tx;
    float acc = 0.f;
    for (int k0 = 0; k0 < K; k0 += 16) {
        As[ty][tx] = (m < M && (k0 + tx) < K) ? A[(size_t)m * lda + k0 + tx] : 0.f;
        Bs[ty][tx] = ((k0 + ty) < K && n < N) ? B[(size_t)(k0 + ty) * ldb + n] : 0.f;
        __syncthreads();
        #pragma unroll
        for (int k = 0; k < 16; k++) acc += As[ty][k] * Bs[k][tx];
        __syncthreads();
    }
    if (m < M && n < N) C[(size_t)m * ldc + n] = acc;
}

// ---------------- bf16 helpers -----------------------------------------------------------
__device__ __forceinline__ uint32_t pack_bf16x2(float lo_elem, float hi_elem) {
    // returns b32 with lo_elem in low half (element k), hi_elem in high half (element k+1)
    uint32_t r;
    asm("cvt.rn.bf16x2.f32 %0, %1, %2;" : "=r"(r) : "f"(hi_elem), "f"(lo_elem));
    return r;
}

__device__ __forceinline__ void cvt_pair(float e0, float e1, uint32_t& hi, uint32_t& lo) {
    hi = pack_bf16x2(e0, e1);
    float h0 = __uint_as_float(hi << 16);
    float h1 = __uint_as_float(hi & 0xffff0000u);
    lo = pack_bf16x2(e0 - h0, e1 - h1);
}

__device__ __forceinline__ void mma_bf16(float* d, const uint32_t* a, uint32_t b0, uint32_t b1) {
    asm volatile(
        "mma.sync.aligned.m16n8k16.row.col.f32.bf16.bf16.f32 "
        "{%0,%1,%2,%3}, {%4,%5,%6,%7}, {%8,%9}, {%0,%1,%2,%3};"
        : "+f"(d[0]), "+f"(d[1]), "+f"(d[2]), "+f"(d[3])
        : "r"(a[0]), "r"(a[1]), "r"(a[2]), "r"(a[3]), "r"(b0), "r"(b1));
}

// ---------------- tensor-core GEMM: C[M,N] = A[M,K] @ B[N,K]^T via 3-term bf16 split -----
// BM=128, BN=128, BK=32. 256 threads = 8 warps (4 M x 2 N), warp tile 32x64.
// M%128==0, K%32==0, grid.x*128 == N. B rows >= Nb treated as zero.
// smem: uint32 tiles (bf16x2 pairs along k), row pitch 20 -> conflict-free frag loads.
#define PITCH 20
#define T_U32 (128 * PITCH)
#define OFF_AH 0
#define OFF_AL T_U32
#define OFF_BH (2 * T_U32)
#define OFF_BL (3 * T_U32)
#define SM_BYTES (4 * T_U32 * 4)

__global__ void __launch_bounds__(256, 2)
mma_gemm_abt(const float* __restrict__ A, int lda,
             const float* __restrict__ B, int ldb, int Nb,
             float* __restrict__ C, int ldc, int K) {
    extern __shared__ uint32_t sm[];
    uint32_t* AH = sm + OFF_AH;
    uint32_t* AL = sm + OFF_AL;
    uint32_t* BH = sm + OFF_BH;
    uint32_t* BL = sm + OFF_BL;

    const int tid  = threadIdx.x;
    const int wid  = tid >> 5;
    const int lane = tid & 31;
    const int m0 = blockIdx.y * 128;
    const int n0 = blockIdx.x * 128;
    const int mbw = (wid & 3) * 32;   // warp M offset
    const int nbw = (wid >> 2) * 64;  // warp N offset
    const int lr = lane >> 2;         // groupID 0..7
    const int lc = lane & 3;          // 0..3

    // fill-loop indices (fixed per thread)
    const int fr  = tid >> 3;         // row 0..31 (+32*i)
    const int fc4 = tid & 7;          // float4 slot 0..7

    float acc[2][8][4] = {};

    const int nchunks = K >> 5;
    for (int ch = 0; ch < nchunks; ch++) {
        const int k0 = ch << 5;
        // ---- A tile: 128 x 32 fp32 -> bf16x2 hi/lo ----
        #pragma unroll
        for (int i = 0; i < 4; i++) {
            int r = fr + i * 32;
            float4 v = *(const float4*)(A + (size_t)(m0 + r) * lda + k0 + fc4 * 4);
            uint32_t h01, l01, h23, l23;
            cvt_pair(v.x, v.y, h01, l01);
            cvt_pair(v.z, v.w, h23, l23);
            int o = r * PITCH + fc4 * 2;
            *(uint2*)(AH + o) = make_uint2(h01, h23);
            *(uint2*)(AL + o) = make_uint2(l01, l23);
        }
        // ---- B tile: 128 x 32 fp32, rows >= Nb zero ----
        #pragma unroll
        for (int i = 0; i < 4; i++) {
            int r = fr + i * 32;
            float4 v = make_float4(0.f, 0.f, 0.f, 0.f);
            if (n0 + r < Nb) v = *(const float4*)(B + (size_t)(n0 + r) * ldb + k0 + fc4 * 4);
            uint32_t h01, l01, h23, l23;
            cvt_pair(v.x, v.y, h01, l01);
            cvt_pair(v.z, v.w, h23, l23);
            int o = r * PITCH + fc4 * 2;
            *(uint2*)(BH + o) = make_uint2(h01, h23);
            *(uint2*)(BL + o) = make_uint2(l01, l23);
        }
        __syncthreads();

        #pragma unroll
        for (int ks = 0; ks < 2; ks++) {
            const int kb = ks * 8 + lc;
            uint32_t ah[2][4], al[2][4];
            #pragma unroll
            for (int t = 0; t < 2; t++) {
                int r0 = (mbw + t * 16 + lr) * PITCH;
                ah[t][0] = AH[r0 + kb];
                ah[t][1] = AH[r0 + 8 * PITCH + kb];
                ah[t][2] = AH[r0 + kb + 4];
                ah[t][3] = AH[r0 + 8 * PITCH + kb + 4];
                al[t][0] = AL[r0 + kb];
                al[t][1] = AL[r0 + 8 * PITCH + kb];
                al[t][2] = AL[r0 + kb + 4];
                al[t][3] = AL[r0 + 8 * PITCH + kb + 4];
            }
            #pragma unroll
            for (int u = 0; u < 8; u++) {
                int rb = (nbw + u * 8 + lr) * PITCH;
                uint32_t bh0 = BH[rb + kb];
                uint32_t bh1 = BH[rb + kb + 4];
                uint32_t bl0 = BL[rb + kb];
                uint32_t bl1 = BL[rb + kb + 4];
                #pragma unroll
                for (int t = 0; t < 2; t++) {
                    mma_bf16(acc[t][u], ah[t], bh0, bh1);   // hi*hi
                    mma_bf16(acc[t][u], ah[t], bl0, bl1);   // hi*lo
                    mma_bf16(acc[t][u], al[t], bh0, bh1);   // lo*hi
                }
            }
        }
        __syncthreads();
    }

    // ---- epilogue ----
    #pragma unroll
    for (int t = 0; t < 2; t++) {
        int row = m0 + mbw + t * 16 + lr;
        #pragma unroll
        for (int u = 0; u < 8; u++) {
            int col = n0 + nbw + u * 8 + lc * 2;
            *(float2*)(C + (size_t)row * ldc + col) = make_float2(acc[t][u][0], acc[t][u][1]);
            *(float2*)(C + (size_t)(row + 8) * ldc + col) = make_float2(acc[t][u][2], acc[t][u][3]);
        }
    }
}

// ---------------- banded softmax mix, smem-tiled ------------------------------------------
__global__ void __launch_bounds__(256)
mix_kernel(const float* __restrict__ z, float* __restrict__ z2) {
    __shared__ float zs[96][64];
    __shared__ float ws[2 * RWIN + 1];
    const int s0 = blockIdx.x * 64;
    const int c0 = blockIdx.y * 64;
    const int b  = blockIdx.z;
    const int tid = threadIdx.x;

    if (tid < 2 * RWIN + 1) ws[tid] = g_e[tid < RWIN ? RWIN - tid : tid - RWIN];

    #pragma unroll
    for (int i = 0; i < 24; i++) {
        int idx = tid + i * 256;
        int r = idx >> 6, c = idx & 63;
        int gs = s0 - 16 + r;
        float v = 0.f;
        if ((unsigned)gs < (unsigned)SS)
            v = z[((size_t)b * SS + gs) * CP + c0 + c];
        zs[r][c] = v;
    }
    __syncthreads();

    const int c = tid & 63;
    #pragma unroll 4
    for (int is = 0; is < 16; is++) {
        int sl = (tid >> 6) + is * 4;
        int s = s0 + sl;
        float Z = 0.f, acc2 = 0.f;
        #pragma unroll
        for (int d = -RWIN; d <= RWIN; ++d) {
            int t = s - d;
            if ((unsigned)t < (unsigned)SS) {
                float w = ws[d + RWIN];
                Z += w;
                acc2 += w * zs[sl + 16 - d][c];
            }
        }
        z2[((size_t)b * SS + s) * CP + c0 + c] = acc2 * (1.f / Z);
    }
}

// ---------------- launch ------------------------------------------------------------------
extern "C" void kernel_launch(void* const* d_in, const int* in_sizes, int n_in,
                              void* d_out, int out_size) {
    const float* x      = (const float*)d_in[0];
    const float* v_low  = (const float*)d_in[5];   // [242, 768]
    const float* v_high = (const float*)d_in[6];   // [256, 242]
    const float* o_low  = (const float*)d_in[7];   // [242, 256]
    const float* o_high = (const float*)d_in[8];   // [768, 242]
    float* out = (float*)d_out;                    // [4, 4096, 768]

    float* z   = nullptr; cudaGetSymbolAddress((void**)&z,   g_z);
    float* z2  = nullptr; cudaGetSymbolAddress((void**)&z2,  g_z2);
    float* T1t = nullptr; cudaGetSymbolAddress((void**)&T1t, g_T1t);
    float* WcT = nullptr; cudaGetSymbolAddress((void**)&WcT, g_WcT);

    cudaFuncSetAttribute(mma_gemm_abt, cudaFuncAttributeMaxDynamicSharedMemorySize, SM_BYTES);

    // 1. band weights
    prep_kernel<<<1, (RWIN + 1) * 32>>>();

    // 2. T1t[242,242] = o_low[242,256] @ v_high[256,242]
    gemm_nn_small<<<dim3((RR + 15) / 16, (RR + 15) / 16), dim3(16, 16)>>>(
        o_low, HK, v_high, RR, T1t, RR, RR, RR, HK);

    // 3. WcT[768,242(pad 256)] = o_high[768,242] @ T1t[242,242]
    gemm_nn_small<<<dim3((RR + 15) / 16, (HH + 15) / 16), dim3(16, 16)>>>(
        o_high, RR, T1t, RR, WcT, CP, HH, RR, RR);

    // 4. z = x @ v_low^T   [16384, 256]
    mma_gemm_abt<<<dim3(CP / 128, (BB * SS) / 128), 256, SM_BYTES>>>(
        x, HH, v_low, HH, RR, z, CP, HH);

    // 5. banded softmax mix
    mix_kernel<<<dim3(SS / 64, CP / 64, BB), 256>>>(z, z2);

    // 6. out = z2 @ WcT^T  [16384, 768]
    mma_gemm_abt<<<dim3(HH / 128, (BB * SS) / 128), 256, SM_BYTES>>>(
        z2, CP, WcT, CP, HH, out, HH, CP);

    (void)in_sizes; (void)n_in; (void)out_size;
}